// round 15
// baseline (speedup 1.0000x reference)
#include <cuda_runtime.h>
#include <cuda_fp16.h>
#include <cuda_bf16.h>
#include <math.h>

#define BB 4
#define CC 64
#define NN 9216       // 96*96
#define NT (NN/64)    // 144 64-key packing tiles
#define QBLK 128      // queries per attention block (4 warps x 32)
#define NRND (NN/128) // 72 staging rounds of 128 keys

// Scratch (static device arrays; no allocation allowed)
__device__ float g_stats[BB * CC * 2];           // mean, rstd per (b,c)
__device__ float g_q[(size_t)BB * NN * CC / 2];  // fp16 A-frag packed (m16n8k16)
__device__ float g_k[(size_t)BB * NN * CC / 2];  // fp16 B-frag packed (uint4 groups)
__device__ float g_v[(size_t)BB * NN * CC / 2];  // fp16 B-frag packed (uint4 groups)
__device__ unsigned g_o[(size_t)BB * NN * 32];   // attention out fp16x2 [b][q][d/2]

// ---------------------------------------------------------------------------
// helpers
// ---------------------------------------------------------------------------
static __device__ __forceinline__ unsigned smem_u32(const void* p) {
    return (unsigned)__cvta_generic_to_shared(p);
}
static __device__ __forceinline__ void cp_async16(unsigned dst, const void* src) {
    asm volatile("cp.async.cg.shared.global [%0], [%1], 16;" :: "r"(dst), "l"(src) : "memory");
}
static __device__ __forceinline__ void cp_commit() {
    asm volatile("cp.async.commit_group;" ::: "memory");
}
static __device__ __forceinline__ unsigned pack_h2(float a, float b) {
    __half2 h = __floats2half2_rn(a, b);
    return *reinterpret_cast<unsigned*>(&h);
}
static __device__ __forceinline__ unsigned ex2_h2(unsigned h) {
    unsigned r;
    asm("ex2.approx.f16x2 %0, %1;" : "=r"(r) : "r"(h));
    return r;
}
static __device__ __forceinline__ unsigned hmax2_u(unsigned a, unsigned b) {
    unsigned r;
    asm("max.f16x2 %0, %1, %2;" : "=r"(r) : "r"(a), "r"(b));
    return r;
}
static __device__ __forceinline__ unsigned hsub2_u(unsigned a, unsigned b) {
    unsigned r;
    asm("sub.f16x2 %0, %1, %2;" : "=r"(r) : "r"(a), "r"(b));
    return r;
}
static __device__ __forceinline__ void mma_f16(float* d, const unsigned* a, uint2 b) {
    asm volatile(
        "mma.sync.aligned.m16n8k16.row.col.f32.f16.f16.f32 "
        "{%0,%1,%2,%3},{%4,%5,%6,%7},{%8,%9},{%0,%1,%2,%3};"
        : "+f"(d[0]), "+f"(d[1]), "+f"(d[2]), "+f"(d[3])
        : "r"(a[0]), "r"(a[1]), "r"(a[2]), "r"(a[3]),
          "r"(b.x), "r"(b.y));
}

// ---------------------------------------------------------------------------
// attn building blocks (forceinline; operate on caller register state)
// ---------------------------------------------------------------------------
static __device__ __forceinline__ void qk_subtile(
    float S[2][8][4], const uint4* Kf4, int lane,
    const unsigned qa[2][4][4], const float mrow[2][2])
{
    float negm[2][2] = {{-mrow[0][0], -mrow[0][1]}, {-mrow[1][0], -mrow[1][1]}};
#pragma unroll
    for (int nb = 0; nb < 8; nb++) {
        uint4 A  = Kf4[(nb * 2 + 0) * 32 + lane];
        uint4 Bv = Kf4[(nb * 2 + 1) * 32 + lane];
        uint2 kf[4];
        kf[0] = make_uint2(A.x, A.y);
        kf[1] = make_uint2(A.z, A.w);
        kf[2] = make_uint2(Bv.x, Bv.y);
        kf[3] = make_uint2(Bv.z, Bv.w);
#pragma unroll
        for (int t = 0; t < 2; t++) {
            S[t][nb][0] = negm[t][0]; S[t][nb][1] = negm[t][0];
            S[t][nb][2] = negm[t][1]; S[t][nb][3] = negm[t][1];
#pragma unroll
            for (int ks = 0; ks < 4; ks++) mma_f16(S[t][nb], qa[t][ks], kf[ks]);
        }
    }
}

static __device__ __forceinline__ void softmax_subtile(
    const float S[2][8][4], unsigned P[2][8][2], float mrow[2][2], float O[2][9][4])
{
#pragma unroll
    for (int t = 0; t < 2; t++)
#pragma unroll
        for (int h = 0; h < 2; h++) {
            unsigned ph[8];
#pragma unroll
            for (int nb = 0; nb < 8; nb++)
                ph[nb] = pack_h2(S[t][nb][2 * h], S[t][nb][2 * h + 1]);
            unsigned t0 = hmax2_u(ph[0], ph[1]);
            unsigned t1 = hmax2_u(ph[2], ph[3]);
            unsigned t2 = hmax2_u(ph[4], ph[5]);
            unsigned t3 = hmax2_u(ph[6], ph[7]);
            unsigned hm = hmax2_u(hmax2_u(t0, t1), hmax2_u(t2, t3));
            hm = hmax2_u(hm, __shfl_xor_sync(0xffffffffu, hm, 1));
            hm = hmax2_u(hm, __shfl_xor_sync(0xffffffffu, hm, 2));
            __half2 hh = *reinterpret_cast<__half2*>(&hm);
            float mxf = fmaxf(__low2float(hh), __high2float(hh));
            if (__any_sync(0xffffffffu, mxf > 0.f)) {
                mxf = fmaxf(mxf, 0.f);
                mrow[t][h] += mxf;
                float corr = exp2f(-mxf);
#pragma unroll
                for (int db = 0; db < 9; db++) {
                    O[t][db][2 * h]     *= corr;
                    O[t][db][2 * h + 1] *= corr;
                }
                unsigned mx2 = pack_h2(mxf, mxf);
#pragma unroll
                for (int nb = 0; nb < 8; nb++) ph[nb] = hsub2_u(ph[nb], mx2);
            }
#pragma unroll
            for (int nb = 0; nb < 8; nb++) P[t][nb][h] = ex2_h2(ph[nb]);
        }
}

static __device__ __forceinline__ void pv_subtile(
    float O[2][9][4], const unsigned P[2][8][2], const uint4* Vf4, int lane, uint2 vones)
{
#pragma unroll
    for (int ks = 0; ks < 4; ks++) {
        unsigned pa[2][4];
#pragma unroll
        for (int t = 0; t < 2; t++) {
            pa[t][0] = P[t][2 * ks][0];
            pa[t][1] = P[t][2 * ks][1];
            pa[t][2] = P[t][2 * ks + 1][0];
            pa[t][3] = P[t][2 * ks + 1][1];
        }
#pragma unroll
        for (int j = 0; j < 4; j++) {
            uint4 Vj = Vf4[(ks * 4 + j) * 32 + lane];
            uint2 v0 = make_uint2(Vj.x, Vj.y);
            uint2 v1 = make_uint2(Vj.z, Vj.w);
            mma_f16(O[0][2 * j],     pa[0], v0);
            mma_f16(O[1][2 * j],     pa[1], v0);
            mma_f16(O[0][2 * j + 1], pa[0], v1);
            mma_f16(O[1][2 * j + 1], pa[1], v1);
        }
        mma_f16(O[0][8], pa[0], vones);
        mma_f16(O[1][8], pa[1], vones);
    }
}

// ---------------------------------------------------------------------------
// Kernel 1: instance-norm statistics. One block per (b,c), 512 threads.
// ---------------------------------------------------------------------------
__global__ __launch_bounds__(512) void stats_kernel(const float* __restrict__ x) {
    int bc = blockIdx.x;
    const float4* xp = (const float4*)(x + (size_t)bc * NN);
    int tid = threadIdx.x;

    float s = 0.f, ss = 0.f;
    for (int i = tid; i < NN / 4; i += 512) {
        float4 v = xp[i];
        s  += v.x + v.y + v.z + v.w;
        ss += v.x * v.x + v.y * v.y + v.z * v.z + v.w * v.w;
    }
#pragma unroll
    for (int off = 16; off > 0; off >>= 1) {
        s  += __shfl_xor_sync(0xffffffffu, s,  off);
        ss += __shfl_xor_sync(0xffffffffu, ss, off);
    }
    __shared__ float ws[16], wss[16];
    int wid = tid >> 5;
    if ((tid & 31) == 0) { ws[wid] = s; wss[wid] = ss; }
    __syncthreads();
    if (tid < 32) {
        float s2  = (tid < 16) ? ws[tid]  : 0.f;
        float ss2 = (tid < 16) ? wss[tid] : 0.f;
#pragma unroll
        for (int off = 8; off > 0; off >>= 1) {
            s2  += __shfl_xor_sync(0xffffffffu, s2,  off);
            ss2 += __shfl_xor_sync(0xffffffffu, ss2, off);
        }
        if (tid == 0) {
            float mean = s2 * (1.0f / NN);
            float var  = ss2 * (1.0f / NN) - mean * mean;
            g_stats[bc * 2]     = mean;
            g_stats[bc * 2 + 1] = rsqrtf(var + 1e-5f);
        }
    }
}

// ---------------------------------------------------------------------------
// Kernel 2: fused norm + Q/K/V 1x1 convs via fp16 tensor cores + frag packing.
// x staging via float4 loads.
// ---------------------------------------------------------------------------
#define QS_OUTS 0
#define QS_HSH  16640
#define QS_WSH  25856
#define QS_MEAN 53504
#define QS_RSTD 53760
#define QKV_SMEM 54016

__global__ __launch_bounds__(256) void qkv_kernel(
    const float* __restrict__ x,
    const float* __restrict__ wq, const float* __restrict__ bq,
    const float* __restrict__ wk, const float* __restrict__ bk,
    const float* __restrict__ wv, const float* __restrict__ bv)
{
    extern __shared__ char smem[];
    float*    outs  = (float*)(smem + QS_OUTS);
    unsigned* hsh   = (unsigned*)(smem + QS_HSH);
    unsigned* wsh   = (unsigned*)(smem + QS_WSH);
    float*    smean = (float*)(smem + QS_MEAN);
    float*    srstd = (float*)(smem + QS_RSTD);

    int tile = blockIdx.x;
    int b    = tile / (NN / 64);
    int n0   = (tile % (NN / 64)) * 64;
    int tid  = threadIdx.x;
    int w    = tid >> 5;
    int lane = tid & 31;
    int rp   = lane >> 2;
    int m    = lane & 3;
    int otile = w & 3;
    int nbb   = (w >> 2) * 4;

    if (tid < 64) {
        smean[tid] = g_stats[(b * 64 + tid) * 2];
        srstd[tid] = g_stats[(b * 64 + tid) * 2 + 1];
    }
    __syncthreads();

    // x staging: float4 loads over both rows of each channel pair
    for (int idx = tid; idx < 512; idx += 256) {
        int cp = idx >> 4;
        int p4 = (idx & 15) << 2;
        const float* r0p = x + ((size_t)b * CC + 2 * cp) * NN + n0 + p4;
        const float* r1p = x + ((size_t)b * CC + 2 * cp + 1) * NN + n0 + p4;
        float4 a  = *(const float4*)r0p;
        float4 b2 = *(const float4*)r1p;
        float m0 = smean[2 * cp],     r0 = srstd[2 * cp];
        float m1 = smean[2 * cp + 1], r1 = srstd[2 * cp + 1];
        hsh[(p4 + 0) * 36 + cp] = pack_h2((a.x - m0) * r0, (b2.x - m1) * r1);
        hsh[(p4 + 1) * 36 + cp] = pack_h2((a.y - m0) * r0, (b2.y - m1) * r1);
        hsh[(p4 + 2) * 36 + cp] = pack_h2((a.z - m0) * r0, (b2.z - m1) * r1);
        hsh[(p4 + 3) * 36 + cp] = pack_h2((a.w - m0) * r0, (b2.w - m1) * r1);
    }
    for (int idx = tid; idx < 6144; idx += 256) {
        int mat = idx >> 11;
        int rem = idx & 2047;
        int o = rem >> 5, cp = rem & 31;
        const float* wsrc = (mat == 0) ? wq : (mat == 1) ? wk : wv;
        float2 wv2 = *(const float2*)(wsrc + o * 64 + 2 * cp);
        wsh[mat * 2304 + o * 36 + cp] = pack_h2(wv2.x, wv2.y);
    }
    __syncthreads();

    const float QSCALE = 0.125f * 1.4426950408889634f;  // C^-0.5 * log2(e)
    size_t qbase = ((size_t)b * (NN / 16) + n0 / 16) * 512;
    size_t kvtile = ((size_t)b * NT + n0 / 64) * 2048;

#pragma unroll
    for (int mat = 0; mat < 3; mat++) {
        float acc[4][4];
#pragma unroll
        for (int nb = 0; nb < 4; nb++) {
            acc[nb][0] = 0.f; acc[nb][1] = 0.f; acc[nb][2] = 0.f; acc[nb][3] = 0.f;
        }
        const unsigned* wm = wsh + mat * 2304;
#pragma unroll
        for (int k = 0; k < 4; k++) {
            unsigned a[4];
            int abase = (otile * 16 + rp) * 36 + k * 8 + m;
            a[0] = wm[abase];
            a[1] = wm[abase + 8 * 36];
            a[2] = wm[abase + 4];
            a[3] = wm[abase + 8 * 36 + 4];
#pragma unroll
            for (int nb = 0; nb < 4; nb++) {
                int p = (nbb + nb) * 8 + rp;
                unsigned b0 = hsh[p * 36 + k * 8 + m];
                unsigned b1 = hsh[p * 36 + k * 8 + m + 4];
                mma_f16(acc[nb], a, make_uint2(b0, b1));
            }
        }

        __syncthreads();
        const float* bias = (mat == 0) ? bq : (mat == 1) ? bk : bv;
        float scale = (mat == 0) ? QSCALE : 1.0f;
        float b0v = bias[otile * 16 + rp];
        float b1v = bias[otile * 16 + rp + 8];
        int o0 = otile * 16 + rp;
#pragma unroll
        for (int nb = 0; nb < 4; nb++) {
            int p0 = (nbb + nb) * 8 + 2 * m;
            outs[p0 * 65 + o0]           = (acc[nb][0] + b0v) * scale;
            outs[(p0 + 1) * 65 + o0]     = (acc[nb][1] + b0v) * scale;
            outs[p0 * 65 + o0 + 8]       = (acc[nb][2] + b1v) * scale;
            outs[(p0 + 1) * 65 + o0 + 8] = (acc[nb][3] + b1v) * scale;
        }
        __syncthreads();

        if (mat == 0) {
            unsigned* qdst = (unsigned*)g_q + qbase;
            for (int idx = tid; idx < 2048; idx += 256) {
                int qb = idx >> 9;
                int ks = (idx >> 7) & 3;
                int ln = (idx >> 2) & 31;
                int rg = idx & 3;
                int row = qb * 16 + (ln >> 2) + ((rg & 1) << 3);
                int c0  = ks * 16 + 2 * (ln & 3) + ((rg & 2) << 2);
                qdst[idx] = pack_h2(outs[row * 65 + c0], outs[row * 65 + c0 + 1]);
            }
        } else if (mat == 1) {
            unsigned* kdst = (unsigned*)g_k + kvtile;
            for (int idx = tid; idx < 2048; idx += 256) {
                int nb   = idx >> 8;
                int pair = (idx >> 7) & 1;
                int ln   = (idx >> 2) & 31;
                int q2   = idx & 3;
                int ks = pair * 2 + (q2 >> 1);
                int rg = q2 & 1;
                int key = nb * 8 + (ln >> 2);
                int kr  = ks * 16 + 2 * (ln & 3) + rg * 8;
                kdst[idx] = pack_h2(outs[key * 65 + kr], outs[key * 65 + kr + 1]);
            }
        } else {
            unsigned* vdst = (unsigned*)g_v + kvtile;
            for (int idx = tid; idx < 2048; idx += 256) {
                int kb = idx >> 9;
                int j  = (idx >> 7) & 3;
                int ln = (idx >> 2) & 31;
                int q2 = idx & 3;
                int db = 2 * j + (q2 >> 1);
                int rg = q2 & 1;
                int key0 = kb * 16 + ((ln & 3) << 1) + (rg << 3);
                int d    = db * 8 + (ln >> 2);
                vdst[idx] = pack_h2(outs[key0 * 65 + d], outs[(key0 + 1) * 65 + d]);
            }
        }
    }
}

// ---------------------------------------------------------------------------
// Kernel 3: tensor-core flash attention, fp16 mma. (exact R12 version)
// ---------------------------------------------------------------------------
__global__ void __launch_bounds__(128, 2) attn_kernel() {
    extern __shared__ uint4 KV[];   // [2][2048]

    int b    = blockIdx.y;
    int w    = threadIdx.x >> 5;
    int lane = threadIdx.x & 31;

    unsigned qa[2][4][4];
    {
        const uint4* qbase = (const uint4*)g_q + ((size_t)b * (NN / 16)) * 128;
        int qblk0 = blockIdx.x * 8 + w * 2;
#pragma unroll
        for (int t = 0; t < 2; t++)
#pragma unroll
            for (int ks = 0; ks < 4; ks++) {
                uint4 v = qbase[((qblk0 + t) * 4 + ks) * 32 + lane];
                qa[t][ks][0] = v.x; qa[t][ks][1] = v.y;
                qa[t][ks][2] = v.z; qa[t][ks][3] = v.w;
            }
    }

    float O[2][9][4];
    float S[2][8][4];
    unsigned P[2][8][2];
    float mrow[2][2];
#pragma unroll
    for (int t = 0; t < 2; t++) {
#pragma unroll
        for (int db = 0; db < 9; db++) {
            O[t][db][0] = 0.f; O[t][db][1] = 0.f; O[t][db][2] = 0.f; O[t][db][3] = 0.f;
        }
        mrow[t][0] = 0.f; mrow[t][1] = 0.f;
    }

    unsigned ones = ((lane >> 2) == 0) ? 0x3C003C00u : 0u;
    uint2 vones = make_uint2(ones, ones);

    const uint4* ksrc = (const uint4*)g_k + (size_t)b * NT * 512;
    const uint4* vsrc = (const uint4*)g_v + (size_t)b * NT * 512;

    {
        unsigned sb = smem_u32(&KV[0]);
        for (int i = threadIdx.x; i < 2048; i += 128) {
            const uint4* src = (i < 1024) ? (ksrc + i) : (vsrc + (i - 1024));
            cp_async16(sb + i * 16, src);
        }
        cp_commit();
    }

    for (int rd = 0; rd < NRND; rd++) {
        int buf = rd & 1;
        asm volatile("cp.async.wait_group 0;" ::: "memory");
        __syncthreads();

        const uint4* Kf0 = &KV[(size_t)buf * 2048];
        const uint4* Vf0 = &KV[(size_t)buf * 2048 + 1024];
        const uint4* Kf1 = Kf0 + 512;
        const uint4* Vf1 = Vf0 + 512;

        qk_subtile(S, Kf0, lane, qa, mrow);

        if (rd + 1 < NRND) {
            unsigned sb = smem_u32(&KV[(buf ^ 1) * 2048]);
            const uint4* kb = ksrc + (size_t)(rd + 1) * 1024;
            const uint4* vb = vsrc + (size_t)(rd + 1) * 1024;
            for (int i = threadIdx.x; i < 2048; i += 128) {
                const uint4* src = (i < 1024) ? (kb + i) : (vb + (i - 1024));
                cp_async16(sb + i * 16, src);
            }
            cp_commit();
        }

        softmax_subtile(S, P, mrow, O);          // sm0
        qk_subtile(S, Kf1, lane, qa, mrow);      // QK1
        pv_subtile(O, P, Vf0, lane, vones);      // PV0
        softmax_subtile(S, P, mrow, O);          // sm1
        pv_subtile(O, P, Vf1, lane, vones);      // PV1
    }

    int q0 = blockIdx.x * QBLK + w * 32 + (lane >> 2);
#pragma unroll
    for (int t = 0; t < 2; t++)
#pragma unroll
        for (int h = 0; h < 2; h++) {
            float l = __shfl_sync(0xffffffffu, O[t][8][2 * h], lane & 28);
            float iv = 1.0f / l;
            int q = q0 + t * 16 + h * 8;
            unsigned* op = g_o + ((size_t)b * NN + q) * 32 + (lane & 3);
#pragma unroll
            for (int db = 0; db < 8; db++)
                op[db * 4] = pack_h2(O[t][db][2 * h] * iv, O[t][db][2 * h + 1] * iv);
        }
}

// ---------------------------------------------------------------------------
// Kernel 4: output 1x1 conv via fp16 mma + residual. (exact R12 version)
// ---------------------------------------------------------------------------
__global__ __launch_bounds__(256) void out_kernel(
    const float* __restrict__ x,
    const float* __restrict__ wo, const float* __restrict__ bo,
    float* __restrict__ out)
{
    __shared__ unsigned osh[64 * 33];
    __shared__ unsigned wsh[64 * 36];
    __shared__ float outs[64 * 65];

    int tile = blockIdx.x;
    int b    = tile / (NN / 64);
    int n0   = (tile % (NN / 64)) * 64;
    int tid  = threadIdx.x;
    int w    = tid >> 5;
    int lane = tid & 31;
    int rp   = lane >> 2;
    int m    = lane & 3;
    int otile = w & 3;
    int nbb   = (w >> 2) * 4;

    for (int idx = tid; idx < 2048; idx += 256) {
        int o = idx >> 5, cp = idx & 31;
        float2 wv2 = *(const float2*)(wo + o * 64 + 2 * cp);
        wsh[o * 36 + cp] = pack_h2(wv2.x, wv2.y);
    }
    {
        const uint4* osrc = (const uint4*)(g_o + ((size_t)b * NN + n0) * 32);
        for (int idx = tid; idx < 512; idx += 256) {
            uint4 v = osrc[idx];
            int p = idx >> 3, c4 = idx & 7;
            unsigned* d = &osh[p * 33 + c4 * 4];
            d[0] = v.x; d[1] = v.y; d[2] = v.z; d[3] = v.w;
        }
    }
    __syncthreads();

    float acc[4][4];
#pragma unroll
    for (int nb = 0; nb < 4; nb++) {
        acc[nb][0] = 0.f; acc[nb][1] = 0.f; acc[nb][2] = 0.f; acc[nb][3] = 0.f;
    }
#pragma unroll
    for (int ks = 0; ks < 4; ks++) {
        unsigned a[4];
        int abase = (otile * 16 + rp) * 36 + ks * 8 + m;
        a[0] = wsh[abase];
        a[1] = wsh[abase + 8 * 36];
        a[2] = wsh[abase + 4];
        a[3] = wsh[abase + 8 * 36 + 4];
#pragma unroll
        for (int nb = 0; nb < 4; nb++) {
            int p = (nbb + nb) * 8 + rp;
            unsigned b0 = osh[p * 33 + ks * 8 + m];
            unsigned b1 = osh[p * 33 + ks * 8 + m + 4];
            mma_f16(acc[nb], a, make_uint2(b0, b1));
        }
    }

    float b0v = bo[otile * 16 + rp];
    float b1v = bo[otile * 16 + rp + 8];
    int o0 = otile * 16 + rp;
#pragma unroll
    for (int nb = 0; nb < 4; nb++) {
        int p0 = (nbb + nb) * 8 + 2 * m;
        outs[p0 * 65 + o0]           = acc[nb][0] + b0v;
        outs[(p0 + 1) * 65 + o0]     = acc[nb][1] + b0v;
        outs[p0 * 65 + o0 + 8]       = acc[nb][2] + b1v;
        outs[(p0 + 1) * 65 + o0 + 8] = acc[nb][3] + b1v;
    }
    __syncthreads();

    int p  = tid & 63;
    int cg = tid >> 6;
#pragma unroll
    for (int i = 0; i < 16; i++) {
        int co = cg * 16 + i;
        size_t oidx = ((size_t)b * CC + co) * NN + n0 + p;
        out[oidx] = x[oidx] + outs[p * 65 + co];
    }
}

// ---------------------------------------------------------------------------
extern "C" void kernel_launch(void* const* d_in, const int* in_sizes, int n_in,
                              void* d_out, int out_size)
{
    const float* x  = (const float*)d_in[0];
    const float* wq = (const float*)d_in[1];
    const float* bq = (const float*)d_in[2];
    const float* wk = (const float*)d_in[3];
    const float* bk = (const float*)d_in[4];
    const float* wv = (const float*)d_in[5];
    const float* bv = (const float*)d_in[6];
    const float* wo = (const float*)d_in[7];
    const float* bo = (const float*)d_in[8];
    float* out = (float*)d_out;

    static bool attr_set = false;
    if (!attr_set) {
        cudaFuncSetAttribute(attn_kernel,
                             cudaFuncAttributeMaxDynamicSharedMemorySize, 65536);
        cudaFuncSetAttribute(qkv_kernel,
                             cudaFuncAttributeMaxDynamicSharedMemorySize, QKV_SMEM);
        attr_set = true;
    }

    stats_kernel<<<BB * CC, 512>>>(x);
    qkv_kernel<<<BB * (NN / 64), 256, QKV_SMEM>>>(x, wq, bq, wk, bk, wv, bv);
    attn_kernel<<<dim3(NN / QBLK, BB), 128, 65536>>>();
    out_kernel<<<BB * (NN / 64), 256>>>(x, wo, bo, out);
}

// round 16
// speedup vs baseline: 1.0179x; 1.0179x over previous
#include <cuda_runtime.h>
#include <cuda_fp16.h>
#include <cuda_bf16.h>
#include <math.h>

#define BB 4
#define CC 64
#define NN 9216       // 96*96
#define NT (NN/64)    // 144 64-key packing tiles
#define QBLK 128      // queries per attention block (4 warps x 32)
#define NRND (NN/128) // 72 staging rounds of 128 keys

// Scratch (static device arrays; no allocation allowed)
__device__ float g_stats[BB * CC * 2];           // mean, rstd per (b,c)
__device__ float g_q[(size_t)BB * NN * CC / 2];  // fp16 A-frag packed (m16n8k16)
__device__ float g_k[(size_t)BB * NN * CC / 2];  // fp16 B-frag packed (uint4 groups)
__device__ float g_v[(size_t)BB * NN * CC / 2];  // fp16 B-frag packed (uint4 groups)
__device__ unsigned g_o[(size_t)BB * NN * 32];   // attention out fp16x2 [b][q][d/2]

// ---------------------------------------------------------------------------
// helpers
// ---------------------------------------------------------------------------
static __device__ __forceinline__ unsigned smem_u32(const void* p) {
    return (unsigned)__cvta_generic_to_shared(p);
}
static __device__ __forceinline__ void cp_async16(unsigned dst, const void* src) {
    asm volatile("cp.async.cg.shared.global [%0], [%1], 16;" :: "r"(dst), "l"(src) : "memory");
}
static __device__ __forceinline__ void cp_commit() {
    asm volatile("cp.async.commit_group;" ::: "memory");
}
static __device__ __forceinline__ unsigned pack_h2(float a, float b) {
    __half2 h = __floats2half2_rn(a, b);
    return *reinterpret_cast<unsigned*>(&h);
}
static __device__ __forceinline__ unsigned ex2_h2(unsigned h) {
    unsigned r;
    asm("ex2.approx.f16x2 %0, %1;" : "=r"(r) : "r"(h));
    return r;
}
static __device__ __forceinline__ unsigned hmax2_u(unsigned a, unsigned b) {
    unsigned r;
    asm("max.f16x2 %0, %1, %2;" : "=r"(r) : "r"(a), "r"(b));
    return r;
}
static __device__ __forceinline__ unsigned hsub2_u(unsigned a, unsigned b) {
    unsigned r;
    asm("sub.f16x2 %0, %1, %2;" : "=r"(r) : "r"(a), "r"(b));
    return r;
}
// fp32-accumulate mma (PV and conv GEMMs)
static __device__ __forceinline__ void mma_f16(float* d, const unsigned* a, uint2 b) {
    asm volatile(
        "mma.sync.aligned.m16n8k16.row.col.f32.f16.f16.f32 "
        "{%0,%1,%2,%3},{%4,%5,%6,%7},{%8,%9},{%0,%1,%2,%3};"
        : "+f"(d[0]), "+f"(d[1]), "+f"(d[2]), "+f"(d[3])
        : "r"(a[0]), "r"(a[1]), "r"(a[2]), "r"(a[3]),
          "r"(b.x), "r"(b.y));
}
// fp16-accumulate mma (QK): d = {c0c1, c2c3} packed f16 pairs
static __device__ __forceinline__ void mma_f16acc(unsigned* d, const unsigned* a, uint2 b) {
    asm volatile(
        "mma.sync.aligned.m16n8k16.row.col.f16.f16.f16.f16 "
        "{%0,%1},{%2,%3,%4,%5},{%6,%7},{%0,%1};"
        : "+r"(d[0]), "+r"(d[1])
        : "r"(a[0]), "r"(a[1]), "r"(a[2]), "r"(a[3]),
          "r"(b.x), "r"(b.y));
}

// ---------------------------------------------------------------------------
// attn building blocks
// ---------------------------------------------------------------------------
// QK with fp16 accumulation: Sh[t][nb][h] = packed f16 pair (cols 2h,2h+1 of row),
// pre-shifted by -mrow (accumulator init).
static __device__ __forceinline__ void qk_subtile(
    unsigned Sh[2][8][2], const uint4* Kf4, int lane,
    const unsigned qa[2][4][4], const float mrow[2][2])
{
    unsigned negm[2][2];
#pragma unroll
    for (int t = 0; t < 2; t++) {
        negm[t][0] = pack_h2(-mrow[t][0], -mrow[t][0]);
        negm[t][1] = pack_h2(-mrow[t][1], -mrow[t][1]);
    }
#pragma unroll
    for (int nb = 0; nb < 8; nb++) {
        uint4 A  = Kf4[(nb * 2 + 0) * 32 + lane];
        uint4 Bv = Kf4[(nb * 2 + 1) * 32 + lane];
        uint2 kf[4];
        kf[0] = make_uint2(A.x, A.y);
        kf[1] = make_uint2(A.z, A.w);
        kf[2] = make_uint2(Bv.x, Bv.y);
        kf[3] = make_uint2(Bv.z, Bv.w);
#pragma unroll
        for (int t = 0; t < 2; t++) {
            Sh[t][nb][0] = negm[t][0];
            Sh[t][nb][1] = negm[t][1];
#pragma unroll
            for (int ks = 0; ks < 4; ks++) mma_f16acc(Sh[t][nb], qa[t][ks], kf[ks]);
        }
    }
}

// softmax: S already packed f16 pairs — no pack step.
static __device__ __forceinline__ void softmax_subtile(
    const unsigned Sh[2][8][2], unsigned P[2][8][2], float mrow[2][2], float O[2][9][4])
{
#pragma unroll
    for (int t = 0; t < 2; t++)
#pragma unroll
        for (int h = 0; h < 2; h++) {
            unsigned ph[8];
#pragma unroll
            for (int nb = 0; nb < 8; nb++) ph[nb] = Sh[t][nb][h];
            unsigned t0 = hmax2_u(ph[0], ph[1]);
            unsigned t1 = hmax2_u(ph[2], ph[3]);
            unsigned t2 = hmax2_u(ph[4], ph[5]);
            unsigned t3 = hmax2_u(ph[6], ph[7]);
            unsigned hm = hmax2_u(hmax2_u(t0, t1), hmax2_u(t2, t3));
            hm = hmax2_u(hm, __shfl_xor_sync(0xffffffffu, hm, 1));
            hm = hmax2_u(hm, __shfl_xor_sync(0xffffffffu, hm, 2));
            __half2 hh = *reinterpret_cast<__half2*>(&hm);
            float mxf = fmaxf(__low2float(hh), __high2float(hh));
            if (__any_sync(0xffffffffu, mxf > 0.f)) {
                mxf = fmaxf(mxf, 0.f);
                mrow[t][h] += mxf;
                float corr = exp2f(-mxf);
#pragma unroll
                for (int db = 0; db < 9; db++) {
                    O[t][db][2 * h]     *= corr;
                    O[t][db][2 * h + 1] *= corr;
                }
                unsigned mx2 = pack_h2(mxf, mxf);
#pragma unroll
                for (int nb = 0; nb < 8; nb++) ph[nb] = hsub2_u(ph[nb], mx2);
            }
#pragma unroll
            for (int nb = 0; nb < 8; nb++) P[t][nb][h] = ex2_h2(ph[nb]);
        }
}

static __device__ __forceinline__ void pv_subtile(
    float O[2][9][4], const unsigned P[2][8][2], const uint4* Vf4, int lane, uint2 vones)
{
#pragma unroll
    for (int ks = 0; ks < 4; ks++) {
        unsigned pa[2][4];
#pragma unroll
        for (int t = 0; t < 2; t++) {
            pa[t][0] = P[t][2 * ks][0];
            pa[t][1] = P[t][2 * ks][1];
            pa[t][2] = P[t][2 * ks + 1][0];
            pa[t][3] = P[t][2 * ks + 1][1];
        }
#pragma unroll
        for (int j = 0; j < 4; j++) {
            uint4 Vj = Vf4[(ks * 4 + j) * 32 + lane];
            uint2 v0 = make_uint2(Vj.x, Vj.y);
            uint2 v1 = make_uint2(Vj.z, Vj.w);
            mma_f16(O[0][2 * j],     pa[0], v0);
            mma_f16(O[1][2 * j],     pa[1], v0);
            mma_f16(O[0][2 * j + 1], pa[0], v1);
            mma_f16(O[1][2 * j + 1], pa[1], v1);
        }
        mma_f16(O[0][8], pa[0], vones);
        mma_f16(O[1][8], pa[1], vones);
    }
}

// ---------------------------------------------------------------------------
// Kernel 1: instance-norm statistics. One block per (b,c), 512 threads.
// ---------------------------------------------------------------------------
__global__ __launch_bounds__(512) void stats_kernel(const float* __restrict__ x) {
    int bc = blockIdx.x;
    const float4* xp = (const float4*)(x + (size_t)bc * NN);
    int tid = threadIdx.x;

    float s = 0.f, ss = 0.f;
    for (int i = tid; i < NN / 4; i += 512) {
        float4 v = xp[i];
        s  += v.x + v.y + v.z + v.w;
        ss += v.x * v.x + v.y * v.y + v.z * v.z + v.w * v.w;
    }
#pragma unroll
    for (int off = 16; off > 0; off >>= 1) {
        s  += __shfl_xor_sync(0xffffffffu, s,  off);
        ss += __shfl_xor_sync(0xffffffffu, ss, off);
    }
    __shared__ float ws[16], wss[16];
    int wid = tid >> 5;
    if ((tid & 31) == 0) { ws[wid] = s; wss[wid] = ss; }
    __syncthreads();
    if (tid < 32) {
        float s2  = (tid < 16) ? ws[tid]  : 0.f;
        float ss2 = (tid < 16) ? wss[tid] : 0.f;
#pragma unroll
        for (int off = 8; off > 0; off >>= 1) {
            s2  += __shfl_xor_sync(0xffffffffu, s2,  off);
            ss2 += __shfl_xor_sync(0xffffffffu, ss2, off);
        }
        if (tid == 0) {
            float mean = s2 * (1.0f / NN);
            float var  = ss2 * (1.0f / NN) - mean * mean;
            g_stats[bc * 2]     = mean;
            g_stats[bc * 2 + 1] = rsqrtf(var + 1e-5f);
        }
    }
}

// ---------------------------------------------------------------------------
// Kernel 2: fused norm + Q/K/V 1x1 convs via fp16 tensor cores + frag packing.
// ---------------------------------------------------------------------------
#define QS_OUTS 0
#define QS_HSH  16640
#define QS_WSH  25856
#define QS_MEAN 53504
#define QS_RSTD 53760
#define QKV_SMEM 54016

__global__ __launch_bounds__(256) void qkv_kernel(
    const float* __restrict__ x,
    const float* __restrict__ wq, const float* __restrict__ bq,
    const float* __restrict__ wk, const float* __restrict__ bk,
    const float* __restrict__ wv, const float* __restrict__ bv)
{
    extern __shared__ char smem[];
    float*    outs  = (float*)(smem + QS_OUTS);
    unsigned* hsh   = (unsigned*)(smem + QS_HSH);
    unsigned* wsh   = (unsigned*)(smem + QS_WSH);
    float*    smean = (float*)(smem + QS_MEAN);
    float*    srstd = (float*)(smem + QS_RSTD);

    int tile = blockIdx.x;
    int b    = tile / (NN / 64);
    int n0   = (tile % (NN / 64)) * 64;
    int tid  = threadIdx.x;
    int w    = tid >> 5;
    int lane = tid & 31;
    int rp   = lane >> 2;
    int m    = lane & 3;
    int otile = w & 3;
    int nbb   = (w >> 2) * 4;

    if (tid < 64) {
        smean[tid] = g_stats[(b * 64 + tid) * 2];
        srstd[tid] = g_stats[(b * 64 + tid) * 2 + 1];
    }
    __syncthreads();

    for (int idx = tid; idx < 512; idx += 256) {
        int cp = idx >> 4;
        int p4 = (idx & 15) << 2;
        const float* r0p = x + ((size_t)b * CC + 2 * cp) * NN + n0 + p4;
        const float* r1p = x + ((size_t)b * CC + 2 * cp + 1) * NN + n0 + p4;
        float4 a  = *(const float4*)r0p;
        float4 b2 = *(const float4*)r1p;
        float m0 = smean[2 * cp],     r0 = srstd[2 * cp];
        float m1 = smean[2 * cp + 1], r1 = srstd[2 * cp + 1];
        hsh[(p4 + 0) * 36 + cp] = pack_h2((a.x - m0) * r0, (b2.x - m1) * r1);
        hsh[(p4 + 1) * 36 + cp] = pack_h2((a.y - m0) * r0, (b2.y - m1) * r1);
        hsh[(p4 + 2) * 36 + cp] = pack_h2((a.z - m0) * r0, (b2.z - m1) * r1);
        hsh[(p4 + 3) * 36 + cp] = pack_h2((a.w - m0) * r0, (b2.w - m1) * r1);
    }
    for (int idx = tid; idx < 6144; idx += 256) {
        int mat = idx >> 11;
        int rem = idx & 2047;
        int o = rem >> 5, cp = rem & 31;
        const float* wsrc = (mat == 0) ? wq : (mat == 1) ? wk : wv;
        float2 wv2 = *(const float2*)(wsrc + o * 64 + 2 * cp);
        wsh[mat * 2304 + o * 36 + cp] = pack_h2(wv2.x, wv2.y);
    }
    __syncthreads();

    const float QSCALE = 0.125f * 1.4426950408889634f;  // C^-0.5 * log2(e)
    size_t qbase = ((size_t)b * (NN / 16) + n0 / 16) * 512;
    size_t kvtile = ((size_t)b * NT + n0 / 64) * 2048;

#pragma unroll
    for (int mat = 0; mat < 3; mat++) {
        float acc[4][4];
#pragma unroll
        for (int nb = 0; nb < 4; nb++) {
            acc[nb][0] = 0.f; acc[nb][1] = 0.f; acc[nb][2] = 0.f; acc[nb][3] = 0.f;
        }
        const unsigned* wm = wsh + mat * 2304;
#pragma unroll
        for (int k = 0; k < 4; k++) {
            unsigned a[4];
            int abase = (otile * 16 + rp) * 36 + k * 8 + m;
            a[0] = wm[abase];
            a[1] = wm[abase + 8 * 36];
            a[2] = wm[abase + 4];
            a[3] = wm[abase + 8 * 36 + 4];
#pragma unroll
            for (int nb = 0; nb < 4; nb++) {
                int p = (nbb + nb) * 8 + rp;
                unsigned b0 = hsh[p * 36 + k * 8 + m];
                unsigned b1 = hsh[p * 36 + k * 8 + m + 4];
                mma_f16(acc[nb], a, make_uint2(b0, b1));
            }
        }

        __syncthreads();
        const float* bias = (mat == 0) ? bq : (mat == 1) ? bk : bv;
        float scale = (mat == 0) ? QSCALE : 1.0f;
        float b0v = bias[otile * 16 + rp];
        float b1v = bias[otile * 16 + rp + 8];
        int o0 = otile * 16 + rp;
#pragma unroll
        for (int nb = 0; nb < 4; nb++) {
            int p0 = (nbb + nb) * 8 + 2 * m;
            outs[p0 * 65 + o0]           = (acc[nb][0] + b0v) * scale;
            outs[(p0 + 1) * 65 + o0]     = (acc[nb][1] + b0v) * scale;
            outs[p0 * 65 + o0 + 8]       = (acc[nb][2] + b1v) * scale;
            outs[(p0 + 1) * 65 + o0 + 8] = (acc[nb][3] + b1v) * scale;
        }
        __syncthreads();

        if (mat == 0) {
            unsigned* qdst = (unsigned*)g_q + qbase;
            for (int idx = tid; idx < 2048; idx += 256) {
                int qb = idx >> 9;
                int ks = (idx >> 7) & 3;
                int ln = (idx >> 2) & 31;
                int rg = idx & 3;
                int row = qb * 16 + (ln >> 2) + ((rg & 1) << 3);
                int c0  = ks * 16 + 2 * (ln & 3) + ((rg & 2) << 2);
                qdst[idx] = pack_h2(outs[row * 65 + c0], outs[row * 65 + c0 + 1]);
            }
        } else if (mat == 1) {
            unsigned* kdst = (unsigned*)g_k + kvtile;
            for (int idx = tid; idx < 2048; idx += 256) {
                int nb   = idx >> 8;
                int pair = (idx >> 7) & 1;
                int ln   = (idx >> 2) & 31;
                int q2   = idx & 3;
                int ks = pair * 2 + (q2 >> 1);
                int rg = q2 & 1;
                int key = nb * 8 + (ln >> 2);
                int kr  = ks * 16 + 2 * (ln & 3) + rg * 8;
                kdst[idx] = pack_h2(outs[key * 65 + kr], outs[key * 65 + kr + 1]);
            }
        } else {
            unsigned* vdst = (unsigned*)g_v + kvtile;
            for (int idx = tid; idx < 2048; idx += 256) {
                int kb = idx >> 9;
                int j  = (idx >> 7) & 3;
                int ln = (idx >> 2) & 31;
                int q2 = idx & 3;
                int db = 2 * j + (q2 >> 1);
                int rg = q2 & 1;
                int key0 = kb * 16 + ((ln & 3) << 1) + (rg << 3);
                int d    = db * 8 + (ln >> 2);
                vdst[idx] = pack_h2(outs[key0 * 65 + d], outs[(key0 + 1) * 65 + d]);
            }
        }
    }
}

// ---------------------------------------------------------------------------
// Kernel 3: tensor-core flash attention. QK in fp16-accum mma (S pre-packed),
// PV in fp32-accum mma. Otherwise exact R12 structure.
// ---------------------------------------------------------------------------
__global__ void __launch_bounds__(128, 2) attn_kernel() {
    extern __shared__ uint4 KV[];   // [2][2048]

    int b    = blockIdx.y;
    int w    = threadIdx.x >> 5;
    int lane = threadIdx.x & 31;

    unsigned qa[2][4][4];
    {
        const uint4* qbase = (const uint4*)g_q + ((size_t)b * (NN / 16)) * 128;
        int qblk0 = blockIdx.x * 8 + w * 2;
#pragma unroll
        for (int t = 0; t < 2; t++)
#pragma unroll
            for (int ks = 0; ks < 4; ks++) {
                uint4 v = qbase[((qblk0 + t) * 4 + ks) * 32 + lane];
                qa[t][ks][0] = v.x; qa[t][ks][1] = v.y;
                qa[t][ks][2] = v.z; qa[t][ks][3] = v.w;
            }
    }

    float O[2][9][4];
    unsigned Sh[2][8][2];
    unsigned P[2][8][2];
    float mrow[2][2];
#pragma unroll
    for (int t = 0; t < 2; t++) {
#pragma unroll
        for (int db = 0; db < 9; db++) {
            O[t][db][0] = 0.f; O[t][db][1] = 0.f; O[t][db][2] = 0.f; O[t][db][3] = 0.f;
        }
        mrow[t][0] = 0.f; mrow[t][1] = 0.f;
    }

    unsigned ones = ((lane >> 2) == 0) ? 0x3C003C00u : 0u;
    uint2 vones = make_uint2(ones, ones);

    const uint4* ksrc = (const uint4*)g_k + (size_t)b * NT * 512;
    const uint4* vsrc = (const uint4*)g_v + (size_t)b * NT * 512;

    {
        unsigned sb = smem_u32(&KV[0]);
        for (int i = threadIdx.x; i < 2048; i += 128) {
            const uint4* src = (i < 1024) ? (ksrc + i) : (vsrc + (i - 1024));
            cp_async16(sb + i * 16, src);
        }
        cp_commit();
    }

    for (int rd = 0; rd < NRND; rd++) {
        int buf = rd & 1;
        asm volatile("cp.async.wait_group 0;" ::: "memory");
        __syncthreads();

        const uint4* Kf0 = &KV[(size_t)buf * 2048];
        const uint4* Vf0 = &KV[(size_t)buf * 2048 + 1024];
        const uint4* Kf1 = Kf0 + 512;
        const uint4* Vf1 = Vf0 + 512;

        qk_subtile(Sh, Kf0, lane, qa, mrow);

        if (rd + 1 < NRND) {
            unsigned sb = smem_u32(&KV[(buf ^ 1) * 2048]);
            const uint4* kb = ksrc + (size_t)(rd + 1) * 1024;
            const uint4* vb = vsrc + (size_t)(rd + 1) * 1024;
            for (int i = threadIdx.x; i < 2048; i += 128) {
                const uint4* src = (i < 1024) ? (kb + i) : (vb + (i - 1024));
                cp_async16(sb + i * 16, src);
            }
            cp_commit();
        }

        softmax_subtile(Sh, P, mrow, O);         // sm0 (consumes Sh into P)
        qk_subtile(Sh, Kf1, lane, qa, mrow);     // QK1 (reuses Sh)
        pv_subtile(O, P, Vf0, lane, vones);      // PV0
        softmax_subtile(Sh, P, mrow, O);         // sm1
        pv_subtile(O, P, Vf1, lane, vones);      // PV1
    }

    int q0 = blockIdx.x * QBLK + w * 32 + (lane >> 2);
#pragma unroll
    for (int t = 0; t < 2; t++)
#pragma unroll
        for (int h = 0; h < 2; h++) {
            float l = __shfl_sync(0xffffffffu, O[t][8][2 * h], lane & 28);
            float iv = 1.0f / l;
            int q = q0 + t * 16 + h * 8;
            unsigned* op = g_o + ((size_t)b * NN + q) * 32 + (lane & 3);
#pragma unroll
            for (int db = 0; db < 8; db++)
                op[db * 4] = pack_h2(O[t][db][2 * h] * iv, O[t][db][2 * h + 1] * iv);
        }
}

// ---------------------------------------------------------------------------
// Kernel 4: output 1x1 conv via fp16 mma + residual. (exact R12 version)
// ---------------------------------------------------------------------------
__global__ __launch_bounds__(256) void out_kernel(
    const float* __restrict__ x,
    const float* __restrict__ wo, const float* __restrict__ bo,
    float* __restrict__ out)
{
    __shared__ unsigned osh[64 * 33];
    __shared__ unsigned wsh[64 * 36];
    __shared__ float outs[64 * 65];

    int tile = blockIdx.x;
    int b    = tile / (NN / 64);
    int n0   = (tile % (NN / 64)) * 64;
    int tid  = threadIdx.x;
    int w    = tid >> 5;
    int lane = tid & 31;
    int rp   = lane >> 2;
    int m    = lane & 3;
    int otile = w & 3;
    int nbb   = (w >> 2) * 4;

    for (int idx = tid; idx < 2048; idx += 256) {
        int o = idx >> 5, cp = idx & 31;
        float2 wv2 = *(const float2*)(wo + o * 64 + 2 * cp);
        wsh[o * 36 + cp] = pack_h2(wv2.x, wv2.y);
    }
    {
        const uint4* osrc = (const uint4*)(g_o + ((size_t)b * NN + n0) * 32);
        for (int idx = tid; idx < 512; idx += 256) {
            uint4 v = osrc[idx];
            int p = idx >> 3, c4 = idx & 7;
            unsigned* d = &osh[p * 33 + c4 * 4];
            d[0] = v.x; d[1] = v.y; d[2] = v.z; d[3] = v.w;
        }
    }
    __syncthreads();

    float acc[4][4];
#pragma unroll
    for (int nb = 0; nb < 4; nb++) {
        acc[nb][0] = 0.f; acc[nb][1] = 0.f; acc[nb][2] = 0.f; acc[nb][3] = 0.f;
    }
#pragma unroll
    for (int ks = 0; ks < 4; ks++) {
        unsigned a[4];
        int abase = (otile * 16 + rp) * 36 + ks * 8 + m;
        a[0] = wsh[abase];
        a[1] = wsh[abase + 8 * 36];
        a[2] = wsh[abase + 4];
        a[3] = wsh[abase + 8 * 36 + 4];
#pragma unroll
        for (int nb = 0; nb < 4; nb++) {
            int p = (nbb + nb) * 8 + rp;
            unsigned b0 = osh[p * 33 + ks * 8 + m];
            unsigned b1 = osh[p * 33 + ks * 8 + m + 4];
            mma_f16(acc[nb], a, make_uint2(b0, b1));
        }
    }

    float b0v = bo[otile * 16 + rp];
    float b1v = bo[otile * 16 + rp + 8];
    int o0 = otile * 16 + rp;
#pragma unroll
    for (int nb = 0; nb < 4; nb++) {
        int p0 = (nbb + nb) * 8 + 2 * m;
        outs[p0 * 65 + o0]           = acc[nb][0] + b0v;
        outs[(p0 + 1) * 65 + o0]     = acc[nb][1] + b0v;
        outs[p0 * 65 + o0 + 8]       = acc[nb][2] + b1v;
        outs[(p0 + 1) * 65 + o0 + 8] = acc[nb][3] + b1v;
    }
    __syncthreads();

    int p  = tid & 63;
    int cg = tid >> 6;
#pragma unroll
    for (int i = 0; i < 16; i++) {
        int co = cg * 16 + i;
        size_t oidx = ((size_t)b * CC + co) * NN + n0 + p;
        out[oidx] = x[oidx] + outs[p * 65 + co];
    }
}

// ---------------------------------------------------------------------------
extern "C" void kernel_launch(void* const* d_in, const int* in_sizes, int n_in,
                              void* d_out, int out_size)
{
    const float* x  = (const float*)d_in[0];
    const float* wq = (const float*)d_in[1];
    const float* bq = (const float*)d_in[2];
    const float* wk = (const float*)d_in[3];
    const float* bk = (const float*)d_in[4];
    const float* wv = (const float*)d_in[5];
    const float* bv = (const float*)d_in[6];
    const float* wo = (const float*)d_in[7];
    const float* bo = (const float*)d_in[8];
    float* out = (float*)d_out;

    static bool attr_set = false;
    if (!attr_set) {
        cudaFuncSetAttribute(attn_kernel,
                             cudaFuncAttributeMaxDynamicSharedMemorySize, 65536);
        cudaFuncSetAttribute(qkv_kernel,
                             cudaFuncAttributeMaxDynamicSharedMemorySize, QKV_SMEM);
        attr_set = true;
    }

    stats_kernel<<<BB * CC, 512>>>(x);
    qkv_kernel<<<BB * (NN / 64), 256, QKV_SMEM>>>(x, wq, bq, wk, bk, wv, bv);
    attn_kernel<<<dim3(NN / QBLK, BB), 128, 65536>>>();
    out_kernel<<<BB * (NN / 64), 256>>>(x, wo, bo, out);
}